// round 3
// baseline (speedup 1.0000x reference)
#include <cuda_runtime.h>

// Problem constants
#define B_  4
#define S_  1024
#define F_  1024
#define H_  16
#define DH_ 64

// Scratch (allocation-free rule: __device__ globals)
__device__ float g_q[B_ * S_ * F_];
__device__ float g_k[B_ * S_ * F_];
__device__ float g_v[B_ * S_ * F_];
__device__ float g_attn[B_ * S_ * F_];

// ----------------------------------------------------------------------------
// GEMM: C[M,N] = A[M,K] @ W[K,N] + bias[N]   (all row-major, fp32)
// Block tile 128x64, K-tile 16, 256 threads, 8x4 register micro-tile.
// blockIdx.z selects among up to 3 (W, bias, C) triples (fused QKV).
// ----------------------------------------------------------------------------
#define GBM 128
#define GBN 64
#define GBK 16

__global__ __launch_bounds__(256)
void gemm_bias_kernel(const float* __restrict__ A,
                      const float* __restrict__ W0, const float* __restrict__ bias0, float* __restrict__ C0,
                      const float* __restrict__ W1, const float* __restrict__ bias1, float* __restrict__ C1,
                      const float* __restrict__ W2, const float* __restrict__ bias2, float* __restrict__ C2,
                      int M, int N, int K)
{
    const float* W; const float* bias; float* C;
    if (blockIdx.z == 0)      { W = W0; bias = bias0; C = C0; }
    else if (blockIdx.z == 1) { W = W1; bias = bias1; C = C1; }
    else                      { W = W2; bias = bias2; C = C2; }

    __shared__ float As[GBK][GBM + 4];   // +4 pad: conflict-light transposed stores
    __shared__ float Ws[GBK][GBN];

    const int tid = threadIdx.x;
    const int tx  = tid & 15;            // 0..15 -> N micro-tile (cols tx*4)
    const int ty  = tid >> 4;            // 0..15 -> M micro-tile (rows ty*8)
    const int m0  = blockIdx.y * GBM;
    const int n0  = blockIdx.x * GBN;

    // A load map: 128 rows x 16 k = 2 float4 per thread
    const int a_r = tid >> 1;            // 0..127
    const int a_k = (tid & 1) * 8;       // 0 or 8
    // W load map: 16 rows x 64 cols = 1 float4 per thread
    const int w_r = tid >> 4;            // 0..15
    const int w_c = (tid & 15) * 4;

    float acc[8][4];
#pragma unroll
    for (int i = 0; i < 8; i++)
#pragma unroll
        for (int j = 0; j < 4; j++) acc[i][j] = 0.f;

    const float* Aptr = A + (size_t)(m0 + a_r) * K + a_k;
    const float* Wptr = W + (size_t)w_r * N + n0 + w_c;

    for (int k0 = 0; k0 < K; k0 += GBK) {
        float4 av0 = *(const float4*)(Aptr + k0);
        float4 av1 = *(const float4*)(Aptr + k0 + 4);
        As[a_k + 0][a_r] = av0.x;
        As[a_k + 1][a_r] = av0.y;
        As[a_k + 2][a_r] = av0.z;
        As[a_k + 3][a_r] = av0.w;
        As[a_k + 4][a_r] = av1.x;
        As[a_k + 5][a_r] = av1.y;
        As[a_k + 6][a_r] = av1.z;
        As[a_k + 7][a_r] = av1.w;
        *(float4*)&Ws[w_r][w_c] = *(const float4*)(Wptr + (size_t)k0 * N);
        __syncthreads();
#pragma unroll
        for (int kk = 0; kk < GBK; kk++) {
            float a[8], w[4];
            *(float4*)&a[0] = *(float4*)&As[kk][ty * 8];
            *(float4*)&a[4] = *(float4*)&As[kk][ty * 8 + 4];
            *(float4*)&w[0] = *(float4*)&Ws[kk][tx * 4];
#pragma unroll
            for (int i = 0; i < 8; i++)
#pragma unroll
                for (int j = 0; j < 4; j++)
                    acc[i][j] += a[i] * w[j];
        }
        __syncthreads();
    }

    float4 bv = *(const float4*)(bias + n0 + tx * 4);
#pragma unroll
    for (int i = 0; i < 8; i++) {
        float4 o;
        o.x = acc[i][0] + bv.x;
        o.y = acc[i][1] + bv.y;
        o.z = acc[i][2] + bv.z;
        o.w = acc[i][3] + bv.w;
        *(float4*)(C + (size_t)(m0 + ty * 8 + i) * N + n0 + tx * 4) = o;
    }
}

// ----------------------------------------------------------------------------
// Fused attention: per CTA = one (b,h) head x 32 query rows.
// Full 32x1024 score rows live in smem:
//   sm = softmax(mask ? str_mat : -1e9)   (str_mat read exactly once)
//   sbuf += (Q K^T) / 64                   (K tile transposed in smem)
//   sbuf = softmax(sbuf)                   (dense: no-op second mask per ref)
//   out  = sbuf @ V  -> g_attn[b, i, h*64+d]
// Head slabs of Q/K/V are contiguous because the reference reshape has no
// transpose: offset (b*16+h)*65536.
// ----------------------------------------------------------------------------
#define RT 32      // query rows per CTA
#define CT 128     // key/value tile

__device__ __forceinline__ void row_softmax(float* row, int lane)
{
    float m = -3.4e38f;
    for (int j = lane * 4; j < S_; j += 128) {
        float4 v = *(float4*)&row[j];
        m = fmaxf(m, fmaxf(fmaxf(v.x, v.y), fmaxf(v.z, v.w)));
    }
#pragma unroll
    for (int o = 16; o; o >>= 1) m = fmaxf(m, __shfl_xor_sync(0xffffffffu, m, o));
    float s = 0.f;
    for (int j = lane * 4; j < S_; j += 128) {
        float4 v = *(float4*)&row[j];
        v.x = __expf(v.x - m);
        v.y = __expf(v.y - m);
        v.z = __expf(v.z - m);
        v.w = __expf(v.w - m);
        s += v.x + v.y + v.z + v.w;
        *(float4*)&row[j] = v;
    }
#pragma unroll
    for (int o = 16; o; o >>= 1) s += __shfl_xor_sync(0xffffffffu, s, o);
    float inv = 1.f / s;
    for (int j = lane * 4; j < S_; j += 128) {
        float4 v = *(float4*)&row[j];
        v.x *= inv; v.y *= inv; v.z *= inv; v.w *= inv;
        *(float4*)&row[j] = v;
    }
}

__global__ __launch_bounds__(256)
void attn_kernel(const float* __restrict__ strm, const float* __restrict__ mask)
{
    extern __shared__ float smem[];
    float* sbuf = smem;                   // RT * S_   = 32768 floats (128 KB)
    float* qs   = sbuf + RT * S_;         // RT * DH_  = 2048   (8 KB)
    float* kvs  = qs + RT * DH_;          // CT * DH_  = 8192   (32 KB)

    const int tid  = threadIdx.x;
    const int lane = tid & 31;
    const int w    = tid >> 5;            // warp 0..7 -> rows w*4 .. w*4+3
    const int bh   = blockIdx.y;          // 0..63 = b*16 + h
    const int b    = bh >> 4;
    const int h    = bh & 15;
    const int i0   = blockIdx.x * RT;

    const float* Qh = g_q + (size_t)bh * S_ * DH_;
    const float* Kh = g_k + (size_t)bh * S_ * DH_;
    const float* Vh = g_v + (size_t)bh * S_ * DH_;

    // ---- load Q rows (contiguous) ----
    for (int idx = tid * 4; idx < RT * DH_; idx += 256 * 4)
        *(float4*)&qs[idx] = *(const float4*)&Qh[(size_t)i0 * DH_ + idx];

    // ---- phase 1: sbuf = (mask==0 ? -1e9 : str_mat) ----
    const float* srow = strm + ((size_t)bh * S_ + i0) * S_;
    const float* mrow = mask + ((size_t)b  * S_ + i0) * S_;
    for (int idx = tid * 4; idx < RT * S_; idx += 256 * 4) {
        float4 mv = *(const float4*)&mrow[idx];
        float4 sv = *(const float4*)&srow[idx];
        float4 o;
        o.x = (mv.x == 0.f) ? -1e9f : sv.x;
        o.y = (mv.y == 0.f) ? -1e9f : sv.y;
        o.z = (mv.z == 0.f) ? -1e9f : sv.z;
        o.w = (mv.w == 0.f) ? -1e9f : sv.w;
        *(float4*)&sbuf[idx] = o;
    }
    __syncthreads();

    // ---- phase 2: sm = softmax(rows) ----
#pragma unroll
    for (int i = 0; i < 4; i++)
        row_softmax(sbuf + (size_t)(w * 4 + i) * S_, lane);

    // ---- phase 3: sbuf += (Q K^T) / 64, K tiles transposed in smem ----
    for (int j0 = 0; j0 < S_; j0 += CT) {
        __syncthreads();   // kvs safe to overwrite; also orders softmax -> reads
        for (int idx = tid * 4; idx < CT * DH_; idx += 256 * 4) {
            int c = idx >> 6;        // key row within tile
            int d = idx & 63;        // head-dim (multiple of 4)
            float4 kv = *(const float4*)&Kh[(size_t)j0 * DH_ + idx];
            kvs[(d + 0) * CT + c] = kv.x;
            kvs[(d + 1) * CT + c] = kv.y;
            kvs[(d + 2) * CT + c] = kv.z;
            kvs[(d + 3) * CT + c] = kv.w;
        }
        __syncthreads();

        float acc[4][4];
#pragma unroll
        for (int i = 0; i < 4; i++)
#pragma unroll
            for (int j = 0; j < 4; j++) acc[i][j] = 0.f;

#pragma unroll 4
        for (int d = 0; d < DH_; d += 4) {
            float qf[4][4];
#pragma unroll
            for (int i = 0; i < 4; i++)
                *(float4*)qf[i] = *(float4*)&qs[(w * 4 + i) * DH_ + d];
#pragma unroll
            for (int t = 0; t < 4; t++) {
                float4 kv = *(float4*)&kvs[(d + t) * CT + lane * 4];
#pragma unroll
                for (int i = 0; i < 4; i++) {
                    acc[i][0] += qf[i][t] * kv.x;
                    acc[i][1] += qf[i][t] * kv.y;
                    acc[i][2] += qf[i][t] * kv.z;
                    acc[i][3] += qf[i][t] * kv.w;
                }
            }
        }
        const float sc = 1.f / 64.f;
#pragma unroll
        for (int i = 0; i < 4; i++) {
            float* p = &sbuf[(size_t)(w * 4 + i) * S_ + j0 + lane * 4];
            float4 v = *(float4*)p;
            v.x += acc[i][0] * sc;
            v.y += acc[i][1] * sc;
            v.z += acc[i][2] * sc;
            v.w += acc[i][3] * sc;
            *(float4*)p = v;
        }
    }
    __syncthreads();

    // ---- phase 4: dense softmax of scores ----
#pragma unroll
    for (int i = 0; i < 4; i++)
        row_softmax(sbuf + (size_t)(w * 4 + i) * S_, lane);

    // ---- phase 5: out = P @ V ----
    float oacc[4][2];
#pragma unroll
    for (int i = 0; i < 4; i++) { oacc[i][0] = 0.f; oacc[i][1] = 0.f; }

    for (int j0 = 0; j0 < S_; j0 += CT) {
        __syncthreads();   // kvs safe; also orders softmax -> sbuf reads
        for (int idx = tid * 4; idx < CT * DH_; idx += 256 * 4)
            *(float4*)&kvs[idx] = *(const float4*)&Vh[(size_t)j0 * DH_ + idx];
        __syncthreads();

#pragma unroll 4
        for (int j = 0; j < CT; j += 4) {
            float pf[4][4];
#pragma unroll
            for (int i = 0; i < 4; i++)
                *(float4*)pf[i] = *(float4*)&sbuf[(size_t)(w * 4 + i) * S_ + j0 + j];
#pragma unroll
            for (int t = 0; t < 4; t++) {
                float2 vv = *(float2*)&kvs[(j + t) * DH_ + lane * 2];
#pragma unroll
                for (int i = 0; i < 4; i++) {
                    oacc[i][0] += pf[i][t] * vv.x;
                    oacc[i][1] += pf[i][t] * vv.y;
                }
            }
        }
    }

    // ---- write to g_attn in transposed [b, s, f] layout ----
    float* outp = g_attn + ((size_t)b * S_ + i0) * F_ + h * DH_;
#pragma unroll
    for (int i = 0; i < 4; i++) {
        float2 o;
        o.x = oacc[i][0];
        o.y = oacc[i][1];
        *(float2*)&outp[(size_t)(w * 4 + i) * F_ + lane * 2] = o;
    }
}

// ----------------------------------------------------------------------------
// Launch
// ----------------------------------------------------------------------------
extern "C" void kernel_launch(void* const* d_in, const int* in_sizes, int n_in,
                              void* d_out, int out_size)
{
    const float* x    = (const float*)d_in[0];
    const float* strm = (const float*)d_in[1];
    const float* mask = (const float*)d_in[2];
    const float* Wq   = (const float*)d_in[3];
    const float* bq   = (const float*)d_in[4];
    const float* Wk   = (const float*)d_in[5];
    const float* bk   = (const float*)d_in[6];
    const float* Wv   = (const float*)d_in[7];
    const float* bv   = (const float*)d_in[8];
    const float* Wo   = (const float*)d_in[9];
    const float* bo   = (const float*)d_in[10];
    float* out = (float*)d_out;

    float *qp, *kp, *vp, *ap;
    cudaGetSymbolAddress((void**)&qp, g_q);
    cudaGetSymbolAddress((void**)&kp, g_k);
    cudaGetSymbolAddress((void**)&vp, g_v);
    cudaGetSymbolAddress((void**)&ap, g_attn);

    const int M = B_ * S_;   // 4096
    const int N = F_;        // 1024
    const int K = F_;        // 1024

    // 1) fused QKV projections
    dim3 g1(N / GBN, M / GBM, 3);
    gemm_bias_kernel<<<g1, 256>>>(x, Wq, bq, qp, Wk, bk, kp, Wv, bv, vp, M, N, K);

    // 2) fused structural-bias softmax + attention
    size_t shm = (size_t)(RT * S_ + RT * DH_ + CT * DH_) * sizeof(float); // 172032 B
    cudaFuncSetAttribute(attn_kernel, cudaFuncAttributeMaxDynamicSharedMemorySize, (int)shm);
    attn_kernel<<<dim3(S_ / RT, B_ * H_), 256, shm>>>(strm, mask);

    // 3) output projection
    dim3 g2(N / GBN, M / GBM, 1);
    gemm_bias_kernel<<<g2, 256>>>(ap, Wo, bo, out, Wo, bo, out, Wo, bo, out, M, N, K);
}